// round 2
// baseline (speedup 1.0000x reference)
#include <cuda_runtime.h>
#include <cstdint>

#define NB 8
#define NC 19
#define NH 512
#define NW 1024
#define HW (NH * NW)                 // 524288
#define CHW ((long long)NC * HW)
#define NPIX ((long long)NB * HW)    // 4194304
#define IGNORE_IDX 255
#define RCE_COEF 9.210340371976182f  // -log(1e-4)
#define A_COEF 0.1
#define B_COEF 1.0

// scratch accumulators: [0]=ce_sum, [1]=rce_sum, [2]=n_valid
__device__ double g_acc[3];

__global__ void zero_acc_kernel() {
    g_acc[0] = 0.0; g_acc[1] = 0.0; g_acc[2] = 0.0;
}

__device__ __forceinline__ float f4_comp(const float4& v, int j) {
    return (j == 0) ? v.x : (j == 1) ? v.y : (j == 2) ? v.z : v.w;
}

__global__ void __launch_bounds__(256)
sce_main_kernel(const float* __restrict__ pred,
                const int* __restrict__ labels) {
    const long long t = (long long)blockIdx.x * blockDim.x + threadIdx.x;
    const long long g = 4LL * t;          // first of 4 pixels for this thread

    float ce_acc = 0.0f, rce_acc = 0.0f, nv_acc = 0.0f;

    if (g < NPIX) {
        const long long n  = g / HW;      // same image for all 4 (HW % 4 == 0)
        const long long hw = g - n * HW;
        const float* base = pred + n * CHW + hw;

        // 19 coalesced float4 loads (one per class plane), all independent → MLP≈19
        float4 v[NC];
        #pragma unroll
        for (int c = 0; c < NC; ++c)
            v[c] = *reinterpret_cast<const float4*>(base + (long long)c * HW);

        // 4 int32 labels in one 16B load (JAX x64 disabled -> labels are int32)
        const int4 lv = *reinterpret_cast<const int4*>(labels + g);
        int y[4];
        y[0] = lv.x; y[1] = lv.y; y[2] = lv.z; y[3] = lv.w;

        #pragma unroll
        for (int j = 0; j < 4; ++j) {
            const int yj = y[j];

            float m  = -3.402823466e+38f;
            float xy = 0.0f;
            #pragma unroll
            for (int c = 0; c < NC; ++c) {
                const float x = f4_comp(v[c], j);
                m  = fmaxf(m, x);
                xy = (c == yj) ? x : xy;
            }

            float s = 0.0f;
            #pragma unroll
            for (int c = 0; c < NC; ++c)
                s += __expf(f4_comp(v[c], j) - m);

            const float logZ  = m + __logf(s);
            const float logpy = xy - logZ;
            float py = __expf(logpy);
            py = fminf(fmaxf(py, 1e-7f), 1.0f);

            // p_sum == 1 to << 1e-3 tolerance (clip at 1e-7 never fires for N(0,1) logits)
            if (yj != IGNORE_IDX) {
                ce_acc  += -logpy;
                rce_acc += RCE_COEF * (1.0f - py);
                nv_acc  += 1.0f;
            }
        }
    }

    // warp reduction
    #pragma unroll
    for (int off = 16; off > 0; off >>= 1) {
        ce_acc  += __shfl_xor_sync(0xFFFFFFFFu, ce_acc,  off);
        rce_acc += __shfl_xor_sync(0xFFFFFFFFu, rce_acc, off);
        nv_acc  += __shfl_xor_sync(0xFFFFFFFFu, nv_acc,  off);
    }

    __shared__ float s_ce[8], s_rce[8], s_nv[8];
    const int wid = threadIdx.x >> 5;
    const int lid = threadIdx.x & 31;
    if (lid == 0) { s_ce[wid] = ce_acc; s_rce[wid] = rce_acc; s_nv[wid] = nv_acc; }
    __syncthreads();

    if (wid == 0) {
        float bc = (lid < 8) ? s_ce[lid]  : 0.0f;
        float br = (lid < 8) ? s_rce[lid] : 0.0f;
        float bn = (lid < 8) ? s_nv[lid]  : 0.0f;
        #pragma unroll
        for (int off = 4; off > 0; off >>= 1) {
            bc += __shfl_xor_sync(0xFFFFFFFFu, bc, off);
            br += __shfl_xor_sync(0xFFFFFFFFu, br, off);
            bn += __shfl_xor_sync(0xFFFFFFFFu, bn, off);
        }
        if (lid == 0) {
            atomicAdd(&g_acc[0], (double)bc);
            atomicAdd(&g_acc[1], (double)br);
            atomicAdd(&g_acc[2], (double)bn);
        }
    }
}

__global__ void finalize_kernel(float* __restrict__ out) {
    const double nv = g_acc[2];
    out[0] = (float)(A_COEF * g_acc[0] / nv + B_COEF * g_acc[1] / nv);
}

extern "C" void kernel_launch(void* const* d_in, const int* in_sizes, int n_in,
                              void* d_out, int out_size) {
    const float* pred = (const float*)d_in[0];
    const int* labels = (const int*)d_in[1];
    float* out = (float*)d_out;

    zero_acc_kernel<<<1, 1>>>();

    const long long nthreads = NPIX / 4;            // 1,048,576
    const int block = 256;
    const int grid = (int)((nthreads + block - 1) / block);  // 4096
    sce_main_kernel<<<grid, block>>>(pred, labels);

    finalize_kernel<<<1, 1>>>(out);
}